// round 8
// baseline (speedup 1.0000x reference)
#include <cuda_runtime.h>
#include <cstdint>

// DurationCalculator: B=256, Y=4096, X=1024
//   weights_argmax[b,y] = duration[b,y] + (y < output_length[b] ? 0 : -10000)
//   durations[b,x]      = #{ y < output_length[b] : duration[b,y] == x }
// duration values lie in [0, X): all valid elements in range; masked ones
// drop below 0 (reference clips them into the discarded bucket).
// Output dtype float32. Layout: [B*Y weights_argmax][B*X durations].
//
// Minimal-traffic design (validated fastest skeleton): one CTA per row,
// private smem histogram, no global partials, no merges, single launch.
// This revision adds ILP: 512 threads x 2 independent int4 loads each
// (MLP=2, both LDGs issued before the dependent atomic chain).

#define B_DIM 256
#define Y_DIM 4096
#define X_DIM 1024
#define MASK_PENALTY (-10000)

__global__ __launch_bounds__(512, 4)
void duration_calc_kernel(const int* __restrict__ duration,
                          const int* __restrict__ output_length,
                          float* __restrict__ weights_out,
                          float* __restrict__ hist_out)
{
    __shared__ int hist[X_DIM];

    const int b   = blockIdx.x;
    const int tid = threadIdx.x;     // 0..511

    const int len = __ldg(&output_length[b]);

    hist[tid]       = 0;
    hist[tid + 512] = 0;
    __syncthreads();

    // Row = 4096 ints = 1024 int4; thread t handles int4s t and t+512.
    const int4* in4 = reinterpret_cast<const int4*>(duration + (size_t)b * Y_DIM);
    float4*    out4 = reinterpret_cast<float4*>(weights_out + (size_t)b * Y_DIM);

    // Two independent loads issued back-to-back (MLP=2).
    const int4 va = in4[tid];
    const int4 vb = in4[tid + 512];

    const int ya = tid * 4;          // elements ya..ya+3
    const int yb = (tid + 512) * 4;  // elements yb..yb+3

    const bool a0 = (ya + 0) < len, a1 = (ya + 1) < len,
               a2 = (ya + 2) < len, a3 = (ya + 3) < len;
    const bool b0 = (yb + 0) < len, b1 = (yb + 1) < len,
               b2 = (yb + 2) < len, b3 = (yb + 3) < len;

    float4 wa, wb;
    wa.x = (float)(va.x + (a0 ? 0 : MASK_PENALTY));
    wa.y = (float)(va.y + (a1 ? 0 : MASK_PENALTY));
    wa.z = (float)(va.z + (a2 ? 0 : MASK_PENALTY));
    wa.w = (float)(va.w + (a3 ? 0 : MASK_PENALTY));
    wb.x = (float)(vb.x + (b0 ? 0 : MASK_PENALTY));
    wb.y = (float)(vb.y + (b1 ? 0 : MASK_PENALTY));
    wb.z = (float)(vb.z + (b2 ? 0 : MASK_PENALTY));
    wb.w = (float)(vb.w + (b3 ? 0 : MASK_PENALTY));

    out4[tid]       = wa;
    out4[tid + 512] = wb;

    if (a0) atomicAdd(&hist[va.x], 1);
    if (a1) atomicAdd(&hist[va.y], 1);
    if (a2) atomicAdd(&hist[va.z], 1);
    if (a3) atomicAdd(&hist[va.w], 1);
    if (b0) atomicAdd(&hist[vb.x], 1);
    if (b1) atomicAdd(&hist[vb.y], 1);
    if (b2) atomicAdd(&hist[vb.z], 1);
    if (b3) atomicAdd(&hist[vb.w], 1);

    __syncthreads();

    // Flush 2 adjacent bins per thread as one float2 store.
    float2 o;
    o.x = (float)hist[2 * tid];
    o.y = (float)hist[2 * tid + 1];
    reinterpret_cast<float2*>(hist_out + (size_t)b * X_DIM)[tid] = o;
}

extern "C" void kernel_launch(void* const* d_in, const int* in_sizes, int n_in,
                              void* d_out, int out_size)
{
    const int* duration      = (const int*)d_in[0];   // (B, Y) int32
    const int* output_length = (const int*)d_in[1];   // (B,)   int32
    // d_in[2] (x_steps) is the compile-time constant X_DIM = 1024.

    float* weights_out = (float*)d_out;                         // B*Y floats
    float* hist_out    = (float*)d_out + (size_t)B_DIM * Y_DIM; // B*X floats

    duration_calc_kernel<<<B_DIM, 512>>>(duration, output_length,
                                         weights_out, hist_out);
}

// round 11
// speedup vs baseline: 1.3084x; 1.3084x over previous
#include <cuda_runtime.h>
#include <cstdint>

// DurationCalculator: B=256, Y=4096, X=1024
//   weights_argmax[b,y] = duration[b,y] + (y < output_length[b] ? 0 : -10000)
//   durations[b,x]      = #{ y < output_length[b] : duration[b,y] == x }
// duration values lie in [0, X): all valid elements in range; masked ones
// drop below 0 (reference clips them into the discarded bucket).
// Output dtype float32. Layout: [B*Y weights_argmax][B*X durations].
//
// Best validated skeleton (R2): one CTA per row, 1024 threads, private smem
// histogram, zero extra global traffic, single launch. This revision:
//  - 2 histogram copies selected by warp parity (halves smem-atomic
//    collision/bank pressure)
//  - int4 LDG hoisted above the first barrier (overlaps load latency with
//    barrier drain; barrier only needs to precede the atomics)

#define B_DIM 256
#define Y_DIM 4096
#define X_DIM 1024
#define MASK_PENALTY (-10000)

__global__ __launch_bounds__(1024, 2)
void duration_calc_kernel(const int* __restrict__ duration,
                          const int* __restrict__ output_length,
                          float* __restrict__ weights_out,
                          float* __restrict__ hist_out)
{
    __shared__ int hist[2][X_DIM];

    const int b   = blockIdx.x;
    const int tid = threadIdx.x;           // 0..1023

    // Zero both histogram copies (2 STS per thread).
    hist[0][tid] = 0;
    hist[1][tid] = 0;

    // Issue the bulk load BEFORE the barrier: it does not touch smem, so its
    // latency overlaps the barrier drain.
    const int4 v = reinterpret_cast<const int4*>(duration + (size_t)b * Y_DIM)[tid];
    const int len = __ldg(&output_length[b]);

    __syncthreads();

    const int y0 = tid * 4;
    const bool m0 = (y0 + 0) < len;
    const bool m1 = (y0 + 1) < len;
    const bool m2 = (y0 + 2) < len;
    const bool m3 = (y0 + 3) < len;

    float4 w;
    w.x = (float)(v.x + (m0 ? 0 : MASK_PENALTY));
    w.y = (float)(v.y + (m1 ? 0 : MASK_PENALTY));
    w.z = (float)(v.z + (m2 ? 0 : MASK_PENALTY));
    w.w = (float)(v.w + (m3 ? 0 : MASK_PENALTY));

    reinterpret_cast<float4*>(weights_out + (size_t)b * Y_DIM)[tid] = w;

    // Warp-parity histogram copy: halves collision degree.
    int* h = hist[(tid >> 5) & 1];
    if (m0) atomicAdd(&h[v.x], 1);
    if (m1) atomicAdd(&h[v.y], 1);
    if (m2) atomicAdd(&h[v.z], 1);
    if (m3) atomicAdd(&h[v.w], 1);

    __syncthreads();

    hist_out[(size_t)b * X_DIM + tid] = (float)(hist[0][tid] + hist[1][tid]);
}

extern "C" void kernel_launch(void* const* d_in, const int* in_sizes, int n_in,
                              void* d_out, int out_size)
{
    const int* duration      = (const int*)d_in[0];   // (B, Y) int32
    const int* output_length = (const int*)d_in[1];   // (B,)   int32
    // d_in[2] (x_steps) is the compile-time constant X_DIM = 1024.

    float* weights_out = (float*)d_out;                         // B*Y floats
    float* hist_out    = (float*)d_out + (size_t)B_DIM * Y_DIM; // B*X floats

    duration_calc_kernel<<<B_DIM, 1024>>>(duration, output_length,
                                          weights_out, hist_out);
}